// round 11
// baseline (speedup 1.0000x reference)
#include <cuda_runtime.h>
#include <math.h>

typedef unsigned long long u64;

// ---------------- packed f32x2 helpers (Blackwell FFMA2 path) ----------------
__device__ __forceinline__ void ffma2(u64 &d, u64 a, u64 b) {
    asm("fma.rn.f32x2 %0, %1, %2, %0;" : "+l"(d) : "l"(a), "l"(b));
}
__device__ __forceinline__ u64 fadd2(u64 a, u64 b) {
    u64 r; asm("add.rn.f32x2 %0, %1, %2;" : "=l"(r) : "l"(a), "l"(b)); return r;
}
__device__ __forceinline__ u64 dup2(float x) {
    u64 r; asm("mov.b64 %0, {%1, %1};" : "=l"(r) : "f"(x)); return r;
}
__device__ __forceinline__ u64 pack2(float lo, float hi) {
    u64 r; asm("mov.b64 %0, {%1, %2};" : "=l"(r) : "f"(lo), "f"(hi)); return r;
}
__device__ __forceinline__ float2 unpk(u64 v) {
    float2 f; asm("mov.b64 {%0, %1}, %2;" : "=f"(f.x), "=f"(f.y) : "l"(v)); return f;
}

// ---------------- scratch (no allocation allowed) ----------------
__device__ float  g_bufA[32u*64*128*128];
__device__ float  g_bufB[32u*64*128*128];
__device__ float  g_bufC[32u*64*32*32];
__device__ u64    g_best[32768];
__device__ float  g_counts[2048];
__device__ float  g_cnorm[2048];
__device__ double g_vq_ss;
__device__ double g_recon_ss;

// ---------------- helpers ----------------
__device__ __forceinline__ float block_sum(float v) {
    __shared__ float sh[256];
    int t = threadIdx.x;
    sh[t] = v; __syncthreads();
    #pragma unroll
    for (int s = 128; s > 0; s >>= 1) {
        if (t < s) sh[t] += sh[t + s];
        __syncthreads();
    }
    return sh[0];
}

__global__ void init_k() {
    int i = blockIdx.x * 256 + threadIdx.x;
    if (i < 32768) g_best[i] = 0xFFFFFFFFFFFFFFFFull;
    if (i < 2048) g_counts[i] = 0.f;
    if (i == 0) { g_vq_ss = 0.0; g_recon_ss = 0.0; }
}

// =====================================================================
// conv 3x3 s1 p1, 64->64, H=W=32. Co-split: block = 4 rows x 32 cols
// x 32 co; thread = 4 spatial x 4 co (2 f32x2 pairs). Grid (16, 32).
// =====================================================================
template<bool PRERELU, bool HAS_BN>
__global__ __launch_bounds__(256) void conv3x3_t(
    const float* __restrict__ in, float* __restrict__ out,
    const float* __restrict__ w, const float* __restrict__ bias,
    const float* __restrict__ bnp)
{
    __shared__ __align__(16) float sIn[8 * 6 * 35];
    __shared__ __align__(16) float sW [8 * 9 * 36];
    const int t = threadIdx.x, ty = t >> 5, tx = t & 31;
    const int row = tx >> 3, col4 = (tx & 7) << 2;
    const int bx = blockIdx.x;
    const int r0 = (bx >> 1) << 2, coBase = (bx & 1) << 5;
    const int n = blockIdx.y;
    const float* inb = in + (size_t)n * 64 * 1024;
    u64 acc[4][2];
    #pragma unroll
    for (int j = 0; j < 4; ++j) { acc[j][0] = 0ull; acc[j][1] = 0ull; }

    for (int ci0 = 0; ci0 < 64; ci0 += 8) {
        __syncthreads();
        for (int i = t; i < 8 * 6 * 34; i += 256) {
            int ci = i / 204, r2 = i - ci * 204, rr = r2 / 34, cc = r2 - rr * 34;
            int gr = r0 - 1 + rr, gc = cc - 1;
            float v = 0.f;
            if ((unsigned)gr < 32u && (unsigned)gc < 32u) {
                v = inb[(ci0 + ci) * 1024 + gr * 32 + gc];
                if (PRERELU) v = fmaxf(v, 0.f);
            }
            sIn[ci * 210 + rr * 35 + cc] = v;
        }
        for (int i = t; i < 8 * 9 * 32; i += 256) {
            int co = i / 72, r2 = i - co * 72, ci = r2 / 9, tap = r2 - ci * 9;
            sW[ci * 324 + tap * 36 + co] = w[(coBase + co) * 576 + (ci0 + ci) * 9 + tap];
        }
        __syncthreads();
        #pragma unroll
        for (int ci = 0; ci < 8; ++ci) {
            const float* sIb = sIn + ci * 210 + row * 35 + col4;
            const float* sWb = sW + ci * 324 + ty * 4;
            #pragma unroll
            for (int kh = 0; kh < 3; ++kh) {
                #pragma unroll
                for (int kw = 0; kw < 3; ++kw) {
                    ulonglong2 wa = *(const ulonglong2*)(sWb + (kh * 3 + kw) * 36);
                    #pragma unroll
                    for (int j = 0; j < 4; ++j) {
                        u64 vd = dup2(sIb[kh * 35 + kw + j]);
                        ffma2(acc[j][0], vd, wa.x);
                        ffma2(acc[j][1], vd, wa.y);
                    }
                }
            }
        }
    }
    const int orow = r0 + row;
    #pragma unroll
    for (int p = 0; p < 2; ++p) {
        float rr2[2][4];
        #pragma unroll
        for (int j = 0; j < 4; ++j) {
            float2 ff = unpk(acc[j][p]);
            rr2[0][j] = ff.x; rr2[1][j] = ff.y;
        }
        #pragma unroll
        for (int l = 0; l < 2; ++l) {
            int co = coBase + ty * 4 + 2 * p + l;
            float b = bias[co];
            float r[4];
            #pragma unroll
            for (int j = 0; j < 4; ++j) r[j] = rr2[l][j] + b;
            if (HAS_BN) {
                float s = bnp[co] * rsqrtf(bnp[192 + co] + 1e-5f);
                float m = bnp[128 + co], bt = bnp[64 + co];
                #pragma unroll
                for (int j = 0; j < 4; ++j) r[j] = (r[j] - m) * s + bt;
            }
            float4 o; o.x = r[0]; o.y = r[1]; o.z = r[2]; o.w = r[3];
            *(float4*)&out[((size_t)n * 64 + co) * 1024 + orow * 32 + col4] = o;
        }
    }
}

// =====================================================================
// conv 1x1, 64->64, HW=1024. Co-split: block = 128 spatial x 32 co.
// Thread = 4 spatial x 4 co. Grid (16, 32).
// =====================================================================
template<bool PRERELU, bool HAS_BN, bool RES>
__global__ __launch_bounds__(256) void conv1x1_t(
    const float* __restrict__ in, const float* __restrict__ res,
    float* __restrict__ out,
    const float* __restrict__ w, const float* __restrict__ bias,
    const float* __restrict__ bnp)
{
    __shared__ __align__(16) float sIn[32 * 128];
    __shared__ __align__(16) float sW [64 * 36];
    const int t = threadIdx.x, ty = t >> 5, tx = t & 31;
    const int bx = blockIdx.x;
    const int sp0 = (bx >> 1) * 128, coBase = (bx & 1) << 5;
    const int n = blockIdx.y;
    for (int i = t; i < 2048; i += 256) {
        int ci = i >> 5, co = i & 31;
        sW[ci * 36 + co] = w[(coBase + co) * 64 + ci];
    }
    u64 acc[4][2];
    #pragma unroll
    for (int j = 0; j < 4; ++j) { acc[j][0] = 0ull; acc[j][1] = 0ull; }
    const float* inb = in + (size_t)n * 64 * 1024 + sp0;
    for (int ch = 0; ch < 2; ++ch) {
        __syncthreads();
        for (int i = t; i < 4096; i += 256) {
            int ci = i >> 7, s = i & 127;
            float v = inb[(ch * 32 + ci) * 1024 + s];
            if (PRERELU) v = fmaxf(v, 0.f);
            sIn[i] = v;
        }
        __syncthreads();
        #pragma unroll 8
        for (int ci = 0; ci < 32; ++ci) {
            float4 v = *(const float4*)&sIn[ci * 128 + tx * 4];
            ulonglong2 wa = *(const ulonglong2*)&sW[(ch * 32 + ci) * 36 + ty * 4];
            u64 vd[4] = {dup2(v.x), dup2(v.y), dup2(v.z), dup2(v.w)};
            #pragma unroll
            for (int j = 0; j < 4; ++j) {
                ffma2(acc[j][0], vd[j], wa.x);
                ffma2(acc[j][1], vd[j], wa.y);
            }
        }
    }
    #pragma unroll
    for (int p = 0; p < 2; ++p) {
        float rr2[2][4];
        #pragma unroll
        for (int j = 0; j < 4; ++j) {
            float2 ff = unpk(acc[j][p]);
            rr2[0][j] = ff.x; rr2[1][j] = ff.y;
        }
        #pragma unroll
        for (int l = 0; l < 2; ++l) {
            int co = coBase + ty * 4 + 2 * p + l;
            float b = bias[co];
            float r[4];
            #pragma unroll
            for (int j = 0; j < 4; ++j) r[j] = rr2[l][j] + b;
            if (HAS_BN) {
                float s = bnp[co] * rsqrtf(bnp[192 + co] + 1e-5f);
                float m = bnp[128 + co], bt = bnp[64 + co];
                #pragma unroll
                for (int j = 0; j < 4; ++j) r[j] = (r[j] - m) * s + bt;
            }
            size_t oi = ((size_t)n * 64 + co) * 1024 + sp0 + tx * 4;
            if (RES) {
                float4 rv = *(const float4*)&res[oi];
                r[0] += rv.x; r[1] += rv.y; r[2] += rv.z; r[3] += rv.w;
            }
            float4 o; o.x = r[0]; o.y = r[1]; o.z = r[2]; o.w = r[3];
            *(float4*)&out[oi] = o;
        }
    }
}

// =====================================================================
// conv k4 s2 p1 -> 64 co, BN fused. Parity-split SMEM input.
// COPT = co per thread (8: full-64 block; 4: co-split, grid.x doubled).
// =====================================================================
template<int CIN, int OW, int C, int COPT, bool RELU>
__global__ __launch_bounds__(256) void conv4s2_t(
    const float* __restrict__ in, float* __restrict__ out,
    const float* __restrict__ w, const float* __restrict__ bias,
    const float* __restrict__ bnp)
{
    constexpr int R = 128 / OW, CPR = OW / 4, HIN = OW * 2;
    constexpr int NR = 2 * R + 2, P = OW + 1, CIST = NR * 2 * P;
    constexpr int COTILE = COPT * 8, PADW = COTILE + 4, NCOB = 64 / COTILE;
    constexpr int NP = COPT / 2;
    __shared__ __align__(16) float sIn[C * CIST];
    __shared__ __align__(16) float sW [C * 16 * PADW];
    const int t = threadIdx.x, ty = t >> 5, tx = t & 31;
    const int row = tx / CPR, col4 = (tx % CPR) * 4;
    const int bx = blockIdx.x;
    const int r0 = (bx / NCOB) * R, coBase = (bx % NCOB) * COTILE;
    const int n = blockIdx.y;
    const float* inb = in + (size_t)n * CIN * HIN * HIN;
    u64 acc[4][NP];
    #pragma unroll
    for (int j = 0; j < 4; ++j)
        #pragma unroll
        for (int p = 0; p < NP; ++p) acc[j][p] = 0ull;

    for (int ci0 = 0; ci0 < CIN; ci0 += C) {
        __syncthreads();
        for (int i = t; i < C * CIST; i += 256) {
            int ci = i / CIST, r2 = i - ci * CIST;
            int rr = r2 / (2 * P), r3 = r2 - rr * 2 * P;
            int p = r3 / P, cc = r3 - p * P;
            int gr = 2 * r0 - 1 + rr;
            int gc = 2 * cc - p;
            float v = 0.f;
            if ((unsigned)gr < (unsigned)HIN && (unsigned)gc < (unsigned)HIN)
                v = inb[(ci0 + ci) * (HIN * HIN) + gr * HIN + gc];
            sIn[i] = v;
        }
        for (int i = t; i < C * 16 * COTILE; i += 256) {
            int co = i / (C * 16), r2 = i - co * C * 16, ci = r2 >> 4, tap = r2 & 15;
            sW[ci * (16 * PADW) + tap * PADW + co] =
                w[((coBase + co) * CIN + ci0 + ci) * 16 + tap];
        }
        __syncthreads();
        #pragma unroll
        for (int ci = 0; ci < C; ++ci) {
            const float* sIb = sIn + ci * CIST + (2 * row) * (2 * P) + col4;
            const float* sWb = sW + ci * (16 * PADW) + ty * COPT;
            #pragma unroll
            for (int kh = 0; kh < 4; ++kh) {
                #pragma unroll
                for (int kw = 0; kw < 4; ++kw) {
                    const float* ip = sIb + kh * (2 * P) + ((kw & 1) ^ 1) * P + (kw >> 1);
                    const ulonglong2* wp = (const ulonglong2*)(sWb + (kh * 4 + kw) * PADW);
                    u64 wv[NP];
                    {
                        ulonglong2 wa = wp[0];
                        wv[0] = wa.x; wv[1] = wa.y;
                        if (NP == 4) {
                            ulonglong2 wb = wp[1];
                            wv[2] = wb.x; wv[3] = wb.y;
                        }
                    }
                    #pragma unroll
                    for (int j = 0; j < 4; ++j) {
                        u64 vd = dup2(ip[j]);
                        #pragma unroll
                        for (int p = 0; p < NP; ++p) ffma2(acc[j][p], vd, wv[p]);
                    }
                }
            }
        }
    }
    const int orow = r0 + row;
    #pragma unroll
    for (int p = 0; p < NP; ++p) {
        float rr2[2][4];
        #pragma unroll
        for (int j = 0; j < 4; ++j) {
            float2 ff = unpk(acc[j][p]);
            rr2[0][j] = ff.x; rr2[1][j] = ff.y;
        }
        #pragma unroll
        for (int l = 0; l < 2; ++l) {
            int co = coBase + ty * COPT + 2 * p + l;
            float b = bias[co];
            float s = bnp[co] * rsqrtf(bnp[192 + co] + 1e-5f);
            float m = bnp[128 + co], bt = bnp[64 + co];
            float r[4];
            #pragma unroll
            for (int j = 0; j < 4; ++j) {
                r[j] = (rr2[l][j] + b - m) * s + bt;
                if (RELU) r[j] = fmaxf(r[j], 0.f);
            }
            float4 o; o.x = r[0]; o.y = r[1]; o.z = r[2]; o.w = r[3];
            *(float4*)&out[((size_t)n * 64 + co) * (OW * OW) + orow * OW + col4] = o;
        }
    }
}

// =====================================================================
// conv-transpose k4 s2 p1, CIN=64. Branch-free 4-tap inner loop.
// Thread = 4 spatial x 8 co (4 f32x2 pairs).
// =====================================================================
template<int COUT, int OUTW, int R, bool PRERELU, bool TANH_LOSS>
__global__ __launch_bounds__(256) void convt_t(
    const float* __restrict__ in, float* __restrict__ out,
    const float* __restrict__ w, const float* __restrict__ bias,
    const float* __restrict__ xref)
{
    constexpr int HIN = OUTW / 2;
    constexpr int NRW = R + 1;
    constexpr int NC  = OUTW / 2 + 2;
    constexpr int NCP = (NC & 1) ? NC : NC + 1;
    constexpr int SPT = R * OUTW;
    constexpr int TXN = SPT / 4;
    constexpr int COS = (COUT == 64) ? 64 : 16;
    __shared__ __align__(16) float sIn[8 * NRW * NCP];
    __shared__ __align__(16) float sW [8 * 16 * 68];
    const int t = threadIdx.x, ty = t / TXN, tx = t % TXN;
    const int row = tx / (OUTW / 4), col4 = (tx % (OUTW / 4)) * 4;
    const int n = blockIdx.y, r0 = blockIdx.x * R;
    const int base_hi = ((r0 + 1) >> 1) - 1;
    const float* inb = in + (size_t)n * 64 * HIN * HIN;
    const int ho = r0 + row;
    const int kh_a = (ho + 1) & 1;
    const int rr_a = ((ho + 1) >> 1) - base_hi;
    int cc0[4], kwp[4];
    #pragma unroll
    for (int j = 0; j < 4; ++j) {
        int wo = col4 + j;
        kwp[j] = (wo + 1) & 1;
        cc0[j] = ((wo + 1) >> 1) + 1;
    }
    u64 acc[4][4];
    #pragma unroll
    for (int j = 0; j < 4; ++j)
        #pragma unroll
        for (int p = 0; p < 4; ++p) acc[j][p] = 0ull;

    for (int ci0 = 0; ci0 < 64; ci0 += 8) {
        __syncthreads();
        for (int i = t; i < 8 * NRW * NCP; i += 256) {
            int ci = i / (NRW * NCP), r2 = i - ci * (NRW * NCP);
            int rr = r2 / NCP, cc = r2 - rr * NCP;
            int gr = base_hi + rr, gc = cc - 1;
            float v = 0.f;
            if ((unsigned)gr < (unsigned)HIN && (unsigned)gc < (unsigned)HIN) {
                v = inb[(ci0 + ci) * (HIN * HIN) + gr * HIN + gc];
                if (PRERELU) v = fmaxf(v, 0.f);
            }
            sIn[i] = v;
        }
        for (int i = t; i < 8 * 16 * COS; i += 256) {
            int ci = i / (16 * COS), r2 = i - ci * (16 * COS);
            int co = r2 >> 4, tap = r2 & 15;
            float v = (co < COUT) ? w[((ci0 + ci) * COUT + co) * 16 + tap] : 0.f;
            sW[ci * 1088 + tap * 68 + co] = v;
        }
        __syncthreads();
        #pragma unroll
        for (int ci = 0; ci < 8; ++ci) {
            const float* rA = sIn + ci * (NRW * NCP) + rr_a * NCP;
            const float* rB = rA - NCP;
            const float* sWb = sW + ci * 1088 + ty * 8;
            #pragma unroll
            for (int jp = 0; jp < 2; ++jp) {
                int t0 = kh_a * 4 + kwp[jp];
                u64 wv[4][4];
                #pragma unroll
                for (int k = 0; k < 4; ++k) {
                    int tap = t0 + (k & 1) * 2 + (k >> 1) * 8;
                    const ulonglong2* wp = (const ulonglong2*)(sWb + tap * 68);
                    ulonglong2 wa = wp[0], wb = wp[1];
                    wv[k][0] = wa.x; wv[k][1] = wa.y; wv[k][2] = wb.x; wv[k][3] = wb.y;
                }
                #pragma unroll
                for (int jj = 0; jj < 2; ++jj) {
                    int j = jp + jj * 2;
                    int ca = cc0[j], cb = ca - 1;
                    u64 da = dup2(rA[ca]), db = dup2(rA[cb]);
                    u64 dc = dup2(rB[ca]), dd = dup2(rB[cb]);
                    #pragma unroll
                    for (int p = 0; p < 4; ++p) {
                        ffma2(acc[j][p], da, wv[0][p]);
                        ffma2(acc[j][p], db, wv[1][p]);
                        ffma2(acc[j][p], dc, wv[2][p]);
                        ffma2(acc[j][p], dd, wv[3][p]);
                    }
                }
            }
        }
    }
    float ls = 0.f;
    #pragma unroll
    for (int p = 0; p < 4; ++p) {
        float rr2[2][4];
        #pragma unroll
        for (int j = 0; j < 4; ++j) {
            float2 ff = unpk(acc[j][p]);
            rr2[0][j] = ff.x; rr2[1][j] = ff.y;
        }
        #pragma unroll
        for (int l = 0; l < 2; ++l) {
            int co = ty * 8 + 2 * p + l;
            if (co < COUT) {
                float b = bias[co];
                size_t oi = ((size_t)n * COUT + co) * ((size_t)OUTW * OUTW) + ho * OUTW + col4;
                float r[4];
                #pragma unroll
                for (int j = 0; j < 4; ++j) {
                    r[j] = rr2[l][j] + b;
                    if (TANH_LOSS) {
                        r[j] = tanhf(r[j]);
                        float d = r[j] - xref[oi + j];
                        ls += d * d;
                    } else {
                        r[j] = fmaxf(r[j], 0.f);
                    }
                }
                float4 o; o.x = r[0]; o.y = r[1]; o.z = r[2]; o.w = r[3];
                *(float4*)&out[oi] = o;
            }
        }
    }
    if (TANH_LOSS) {
        float s = block_sum(ls);
        if (t == 0) atomicAdd(&g_recon_ss, (double)s);
    }
}

// ---------------- VQ ----------------
__global__ void cnorm_k(const float* __restrict__ cb) {
    int k = blockIdx.x * 256 + threadIdx.x;
    if (k < 2048) {
        float s = 0.f;
        #pragma unroll
        for (int d = 0; d < 64; ++d) { float c = cb[k * 64 + d]; s += c * c; }
        g_cnorm[k] = s;
    }
}

// grid (256 row-blocks, 4 codebook quarters), 128 threads, 1 row/thread.
__global__ __launch_bounds__(128) void vq_assign_k(
    const float* __restrict__ z, const float* __restrict__ cb)
{
    __shared__ __align__(16) float4 sc[128 * 16];
    __shared__ float  sn[128];
    const int row = blockIdx.x * 128 + threadIdx.x;
    const int q0 = blockIdx.y * 512;
    const int b = row >> 10, hw = row & 1023;
    u64 zr2[32];
    const float* zp = z + ((size_t)b * 64) * 1024 + hw;
    #pragma unroll
    for (int d2 = 0; d2 < 32; ++d2)
        zr2[d2] = pack2(zp[(2 * d2) * 1024], zp[(2 * d2 + 1) * 1024]);
    float best = 3.4e38f; int bi = 0;
    const float4* cb4 = (const float4*)cb;
    for (int k0 = q0; k0 < q0 + 512; k0 += 128) {
        __syncthreads();
        for (int i = threadIdx.x; i < 128 * 16; i += 128) sc[i] = cb4[k0 * 16 + i];
        sn[threadIdx.x] = g_cnorm[k0 + threadIdx.x];
        __syncthreads();
        for (int kk = 0; kk < 128; ++kk) {
            const ulonglong2* cp = (const ulonglong2*)(sc + kk * 16);
            u64 a0 = 0ull, a1 = 0ull, a2 = 0ull, a3 = 0ull;
            #pragma unroll
            for (int j = 0; j < 8; ++j) {
                ulonglong2 c0 = cp[2 * j], c1 = cp[2 * j + 1];
                ffma2(a0, zr2[4 * j + 0], c0.x);
                ffma2(a1, zr2[4 * j + 1], c0.y);
                ffma2(a2, zr2[4 * j + 2], c1.x);
                ffma2(a3, zr2[4 * j + 3], c1.y);
            }
            u64 s2 = fadd2(fadd2(a0, a1), fadd2(a2, a3));
            float2 f = unpk(s2);
            float dist = sn[kk] - 2.f * (f.x + f.y);
            if (dist < best) { best = dist; bi = k0 + kk; }
        }
    }
    unsigned int fb = __float_as_uint(best);
    unsigned int key = fb ^ (((int)fb >> 31) | 0x80000000u);
    u64 packed = ((u64)key << 32) | (unsigned)bi;
    atomicMin(&g_best[row], packed);
}

__global__ __launch_bounds__(256) void vq_gather_k(
    const float* __restrict__ z, const float* __restrict__ cb,
    float* __restrict__ quant)
{
    int gid = blockIdx.x * 256 + threadIdx.x;
    int b = gid >> 16;
    int rem = gid & 65535;
    int d = rem >> 10;
    int hw = rem & 1023;
    int k = (int)(unsigned)(g_best[(b << 10) + hw] & 0xFFFFFFFFull);
    float q = cb[k * 64 + d];
    float zv = z[gid];
    quant[gid] = q;
    float diff = q - zv;
    float s = block_sum(diff * diff);
    if (threadIdx.x == 0) atomicAdd(&g_vq_ss, (double)s);
}

__global__ void vq_counts_k() {
    int i = blockIdx.x * 256 + threadIdx.x;
    if (i < 32768) {
        int k = (int)(unsigned)(g_best[i] & 0xFFFFFFFFull);
        atomicAdd(&g_counts[k], 1.0f);
    }
}

// ---------------- finalize ----------------
__global__ void finalize_k(float* __restrict__ out2) {
    float s = 0.f;
    for (int k = threadIdx.x; k < 2048; k += 256) {
        float p = g_counts[k] * (1.0f / 32768.0f);
        s += p * logf(p + 1e-10f);
    }
    float tot = block_sum(s);
    if (threadIdx.x == 0) {
        float perp = expf(-tot);
        float loss = (float)(g_recon_ss / 31457280.0 + 1.25 * (g_vq_ss / 2097152.0));
        out2[0] = loss;
        out2[1] = perp;
    }
}

// ---------------- launcher ----------------
extern "C" void kernel_launch(void* const* d_in, const int* in_sizes, int n_in,
                              void* d_out, int out_size) {
    const float* x          = (const float*)d_in[0];
    const float* ew1        = (const float*)d_in[1];
    const float* eb1        = (const float*)d_in[2];
    const float* ew2        = (const float*)d_in[3];
    const float* eb2        = (const float*)d_in[4];
    const float* ew3        = (const float*)d_in[5];
    const float* eb3        = (const float*)d_in[6];
    const float* enc_bn     = (const float*)d_in[7];
    const float* enc_res_w3 = (const float*)d_in[8];
    const float* enc_res_b3 = (const float*)d_in[9];
    const float* enc_res_w1 = (const float*)d_in[10];
    const float* enc_res_b1 = (const float*)d_in[11];
    const float* enc_res_bn = (const float*)d_in[12];
    const float* enc_out_w  = (const float*)d_in[13];
    const float* enc_out_b  = (const float*)d_in[14];
    const float* codebook   = (const float*)d_in[15];
    const float* dec_in_w   = (const float*)d_in[16];
    const float* dec_in_b   = (const float*)d_in[17];
    const float* dec_res_w3 = (const float*)d_in[18];
    const float* dec_res_b3 = (const float*)d_in[19];
    const float* dec_res_w1 = (const float*)d_in[20];
    const float* dec_res_b1 = (const float*)d_in[21];
    const float* dec_res_bn = (const float*)d_in[22];
    const float* dt_w1      = (const float*)d_in[23];
    const float* dt_b1      = (const float*)d_in[24];
    const float* dt_w2      = (const float*)d_in[25];
    const float* dt_b2      = (const float*)d_in[26];
    const float* dt_w3      = (const float*)d_in[27];
    const float* dt_b3      = (const float*)d_in[28];

    void *pa, *pb, *pc;
    cudaGetSymbolAddress(&pa, g_bufA);
    cudaGetSymbolAddress(&pb, g_bufB);
    cudaGetSymbolAddress(&pc, g_bufC);
    float* A  = (float*)pa;
    float* Bb = (float*)pb;
    float* Cc = (float*)pc;
    float* out = (float*)d_out;

    init_k<<<128, 256>>>();

    // ---- Encoder ----
    conv4s2_t<15, 128, 5, 8, true ><<<dim3(128, 32), 256>>>(x,  A,  ew1, eb1, enc_bn);
    conv4s2_t<64, 64,  4, 8, true ><<<dim3(32, 32),  256>>>(A,  Bb, ew2, eb2, enc_bn + 256);
    conv4s2_t<64, 32,  4, 4, false><<<dim3(16, 32),  256>>>(Bb, A,  ew3, eb3, enc_bn + 512);
    for (int i = 0; i < 4; ++i) {
        conv3x3_t<true, true><<<dim3(16, 32), 256>>>(
            A, Bb, enc_res_w3 + (size_t)i * 36864, enc_res_b3 + i * 64,
            enc_res_bn + i * 512);
        conv1x1_t<true, true, true><<<dim3(16, 32), 256>>>(
            Bb, A, A, enc_res_w1 + (size_t)i * 4096, enc_res_b1 + i * 64,
            enc_res_bn + i * 512 + 256);
    }
    conv1x1_t<false, false, false><<<dim3(16, 32), 256>>>(
        A, nullptr, Bb, enc_out_w, enc_out_b, nullptr);     // z -> Bb

    // ---- VQ ----
    cnorm_k<<<8, 256>>>(codebook);
    vq_assign_k<<<dim3(256, 4), 128>>>(Bb, codebook);
    vq_gather_k<<<8192, 256>>>(Bb, codebook, A);            // quant -> A
    vq_counts_k<<<128, 256>>>();

    // ---- Decoder ----
    conv3x3_t<false, false><<<dim3(16, 32), 256>>>(A, Bb, dec_in_w, dec_in_b, nullptr);
    for (int i = 0; i < 4; ++i) {
        conv3x3_t<true, true><<<dim3(16, 32), 256>>>(
            Bb, Cc, dec_res_w3 + (size_t)i * 36864, dec_res_b3 + i * 64,
            dec_res_bn + i * 512);
        conv1x1_t<true, true, true><<<dim3(16, 32), 256>>>(
            Cc, Bb, Bb, dec_res_w1 + (size_t)i * 4096, dec_res_b1 + i * 64,
            dec_res_bn + i * 512 + 256);
    }
    convt_t<64, 64,  2, true,  false><<<dim3(32, 32),  256>>>(Bb, A,   dt_w1, dt_b1, nullptr);
    convt_t<64, 128, 1, false, false><<<dim3(128, 32), 256>>>(A,  Bb,  dt_w2, dt_b2, nullptr);
    convt_t<15, 256, 2, false, true ><<<dim3(128, 32), 256>>>(Bb, out, dt_w3, dt_b3, x);

    finalize_k<<<1, 256>>>(out + (out_size - 2));
}

// round 14
// speedup vs baseline: 1.0270x; 1.0270x over previous
#include <cuda_runtime.h>
#include <math.h>

typedef unsigned long long u64;

// ---------------- packed f32x2 helpers (Blackwell FFMA2 path) ----------------
__device__ __forceinline__ void ffma2(u64 &d, u64 a, u64 b) {
    asm("fma.rn.f32x2 %0, %1, %2, %0;" : "+l"(d) : "l"(a), "l"(b));
}
__device__ __forceinline__ u64 fadd2(u64 a, u64 b) {
    u64 r; asm("add.rn.f32x2 %0, %1, %2;" : "=l"(r) : "l"(a), "l"(b)); return r;
}
__device__ __forceinline__ u64 dup2(float x) {
    u64 r; asm("mov.b64 %0, {%1, %1};" : "=l"(r) : "f"(x)); return r;
}
__device__ __forceinline__ u64 pack2(float lo, float hi) {
    u64 r; asm("mov.b64 %0, {%1, %2};" : "=l"(r) : "f"(lo), "f"(hi)); return r;
}
__device__ __forceinline__ float2 unpk(u64 v) {
    float2 f; asm("mov.b64 {%0, %1}, %2;" : "=f"(f.x), "=f"(f.y) : "l"(v)); return f;
}

// ---------------- tf32 mma helpers ----------------
__device__ __forceinline__ unsigned f2tf(float v) {
    unsigned r; asm("cvt.rna.tf32.f32 %0, %1;" : "=r"(r) : "f"(v)); return r;
}
__device__ __forceinline__ void mma_tf32(
    float &d0, float &d1, float &d2, float &d3,
    unsigned a0, unsigned a1, unsigned a2, unsigned a3,
    unsigned b0, unsigned b1)
{
    asm("mma.sync.aligned.m16n8k8.row.col.f32.tf32.tf32.f32 "
        "{%0,%1,%2,%3}, {%4,%5,%6,%7}, {%8,%9}, {%0,%1,%2,%3};"
        : "+f"(d0), "+f"(d1), "+f"(d2), "+f"(d3)
        : "r"(a0), "r"(a1), "r"(a2), "r"(a3), "r"(b0), "r"(b1));
}

// ---------------- scratch (no allocation allowed) ----------------
__device__ float  g_bufA[32u*64*128*128];
__device__ float  g_bufB[32u*64*128*128];
__device__ float  g_bufC[32u*64*32*32];
__device__ u64    g_best[32768];
__device__ float  g_counts[2048];
__device__ float  g_cnorm[2048];
__device__ double g_vq_ss;
__device__ double g_recon_ss;

// ---------------- helpers ----------------
__device__ __forceinline__ float block_sum(float v) {
    __shared__ float sh[256];
    int t = threadIdx.x;
    sh[t] = v; __syncthreads();
    #pragma unroll
    for (int s = 128; s > 0; s >>= 1) {
        if (t < s) sh[t] += sh[t + s];
        __syncthreads();
    }
    return sh[0];
}

__global__ void init_k() {
    int i = blockIdx.x * 256 + threadIdx.x;
    if (i < 32768) g_best[i] = 0xFFFFFFFFFFFFFFFFull;
    if (i < 2048) g_counts[i] = 0.f;
    if (i == 0) { g_vq_ss = 0.0; g_recon_ss = 0.0; }
}

// =====================================================================
// conv 3x3 s1 p1, 64->64, H=W=32, tf32 tensor cores.
// GEMM: A = W [M=64co x K], B = im2col inputs [K x N=128 sp], K=576.
// Block: 256 thr = 8 warps; warp (mw=w&3 -> 16 co, nw=w>>2 -> 64 sp).
// Grid (8 row-tiles, 32 img).
// =====================================================================
template<bool PRERELU, bool HAS_BN>
__global__ __launch_bounds__(256) void conv3x3_mma(
    const float* __restrict__ in, float* __restrict__ out,
    const float* __restrict__ w, const float* __restrict__ bias,
    const float* __restrict__ bnp)
{
    __shared__ unsigned sIn[8 * 6 * 36];    // [ci8][row6][pitch36] tf32 bits
    __shared__ unsigned sW [9 * 8 * 72];    // [tap][ci8][pitch72]  tf32 bits
    const int t = threadIdx.x, lane = t & 31, wid = t >> 5;
    const int mw = wid & 3, nw = wid >> 1 >> 1;   // mw: co slice, nw: sp half
    const int grp = lane >> 2, tig = lane & 3;
    const int n = blockIdx.y, r0 = blockIdx.x << 2;
    const int coW = mw * 16;
    const float* inb = in + (size_t)n * 64 * 1024;
    float acc[8][4];
    #pragma unroll
    for (int nt = 0; nt < 8; ++nt)
        #pragma unroll
        for (int i = 0; i < 4; ++i) acc[nt][i] = 0.f;

    for (int ci0 = 0; ci0 < 64; ci0 += 8) {
        __syncthreads();
        for (int i = t; i < 8 * 6 * 34; i += 256) {
            int ci = i / 204, r2 = i - ci * 204, rr = r2 / 34, cc = r2 - rr * 34;
            int gr = r0 - 1 + rr, gc = cc - 1;
            float v = 0.f;
            if ((unsigned)gr < 32u && (unsigned)gc < 32u) {
                v = inb[(ci0 + ci) * 1024 + gr * 32 + gc];
                if (PRERELU) v = fmaxf(v, 0.f);
            }
            sIn[ci * 216 + rr * 36 + cc] = f2tf(v);
        }
        for (int i = t; i < 9 * 8 * 64; i += 256) {
            int tap = i >> 9, r2 = i & 511, ci = r2 >> 6, co = r2 & 63;
            sW[(tap * 8 + ci) * 72 + co] =
                f2tf(w[co * 576 + (ci0 + ci) * 9 + tap]);
        }
        __syncthreads();
        #pragma unroll
        for (int kh = 0; kh < 3; ++kh) {
            #pragma unroll
            for (int kw = 0; kw < 3; ++kw) {
                const unsigned* wrow = sW + ((kh * 3 + kw) * 8) * 72 + coW + grp;
                unsigned a0 = wrow[tig * 72];
                unsigned a1 = wrow[tig * 72 + 8];
                unsigned a2 = wrow[(tig + 4) * 72];
                unsigned a3 = wrow[(tig + 4) * 72 + 8];
                #pragma unroll
                for (int nt = 0; nt < 8; ++nt) {
                    int rr = 2 * nw + (nt >> 2) + kh;
                    int cc = (nt & 3) * 8 + grp + kw;
                    unsigned b0 = sIn[tig * 216 + rr * 36 + cc];
                    unsigned b1 = sIn[(tig + 4) * 216 + rr * 36 + cc];
                    mma_tf32(acc[nt][0], acc[nt][1], acc[nt][2], acc[nt][3],
                             a0, a1, a2, a3, b0, b1);
                }
            }
        }
    }
    // epilogue: r = acc*sc + sh  (sc/sh fold bias+BN)
    const int co1 = coW + grp, co2 = co1 + 8;
    float sc1 = 1.f, sc2 = 1.f, sh1 = bias[co1], sh2 = bias[co2];
    if (HAS_BN) {
        sc1 = bnp[co1] * rsqrtf(bnp[192 + co1] + 1e-5f);
        sc2 = bnp[co2] * rsqrtf(bnp[192 + co2] + 1e-5f);
        sh1 = (sh1 - bnp[128 + co1]) * sc1 + bnp[64 + co1];
        sh2 = (sh2 - bnp[128 + co2]) * sc2 + bnp[64 + co2];
    }
    float* ob = out + (size_t)n * 64 * 1024;
    #pragma unroll
    for (int nt = 0; nt < 8; ++nt) {
        int sp = (r0 + 2 * nw + (nt >> 2)) * 32 + (nt & 3) * 8 + 2 * tig;
        float2 o1; o1.x = acc[nt][0] * sc1 + sh1; o1.y = acc[nt][1] * sc1 + sh1;
        float2 o2; o2.x = acc[nt][2] * sc2 + sh2; o2.y = acc[nt][3] * sc2 + sh2;
        *(float2*)&ob[co1 * 1024 + sp] = o1;
        *(float2*)&ob[co2 * 1024 + sp] = o2;
    }
}

// =====================================================================
// conv 1x1, 64->64, HW=1024, tf32 tensor cores. Same warp layout;
// N = 128 spatial (linear), K = 64. Grid (8, 32).
// =====================================================================
template<bool PRERELU, bool HAS_BN, bool RES>
__global__ __launch_bounds__(256) void conv1x1_mma(
    const float* __restrict__ in, const float* __restrict__ res,
    float* __restrict__ out,
    const float* __restrict__ w, const float* __restrict__ bias,
    const float* __restrict__ bnp)
{
    __shared__ unsigned sIn[8 * 136];     // [ci8][pitch136]
    __shared__ unsigned sW [64 * 72];     // [ci][pitch72]
    const int t = threadIdx.x, lane = t & 31, wid = t >> 5;
    const int mw = wid & 3, nw = wid >> 2;
    const int grp = lane >> 2, tig = lane & 3;
    const int n = blockIdx.y, sp0 = blockIdx.x * 128;
    const int coW = mw * 16;
    for (int i = t; i < 4096; i += 256) {
        int ci = i >> 6, co = i & 63;
        sW[ci * 72 + co] = f2tf(w[co * 64 + ci]);
    }
    float acc[8][4];
    #pragma unroll
    for (int nt = 0; nt < 8; ++nt)
        #pragma unroll
        for (int i = 0; i < 4; ++i) acc[nt][i] = 0.f;
    const float* inb = in + (size_t)n * 64 * 1024 + sp0;
    for (int ci0 = 0; ci0 < 64; ci0 += 8) {
        __syncthreads();
        for (int i = t; i < 1024; i += 256) {
            int ci = i >> 7, s = i & 127;
            float v = inb[(ci0 + ci) * 1024 + s];
            if (PRERELU) v = fmaxf(v, 0.f);
            sIn[ci * 136 + s] = f2tf(v);
        }
        __syncthreads();
        const unsigned* wrow = sW + ci0 * 72 + coW + grp;
        unsigned a0 = wrow[tig * 72];
        unsigned a1 = wrow[tig * 72 + 8];
        unsigned a2 = wrow[(tig + 4) * 72];
        unsigned a3 = wrow[(tig + 4) * 72 + 8];
        #pragma unroll
        for (int nt = 0; nt < 8; ++nt) {
            int cc = nw * 64 + nt * 8 + grp;
            unsigned b0 = sIn[tig * 136 + cc];
            unsigned b1 = sIn[(tig + 4) * 136 + cc];
            mma_tf32(acc[nt][0], acc[nt][1], acc[nt][2], acc[nt][3],
                     a0, a1, a2, a3, b0, b1);
        }
    }
    const int co1 = coW + grp, co2 = co1 + 8;
    float sc1 = 1.f, sc2 = 1.f, sh1 = bias[co1], sh2 = bias[co2];
    if (HAS_BN) {
        sc1 = bnp[co1] * rsqrtf(bnp[192 + co1] + 1e-5f);
        sc2 = bnp[co2] * rsqrtf(bnp[192 + co2] + 1e-5f);
        sh1 = (sh1 - bnp[128 + co1]) * sc1 + bnp[64 + co1];
        sh2 = (sh2 - bnp[128 + co2]) * sc2 + bnp[64 + co2];
    }
    float* ob = out + (size_t)n * 64 * 1024 + sp0;
    const float* rb = RES ? res + (size_t)n * 64 * 1024 + sp0 : nullptr;
    #pragma unroll
    for (int nt = 0; nt < 8; ++nt) {
        int sp = nw * 64 + nt * 8 + 2 * tig;
        float2 o1; o1.x = acc[nt][0] * sc1 + sh1; o1.y = acc[nt][1] * sc1 + sh1;
        float2 o2; o2.x = acc[nt][2] * sc2 + sh2; o2.y = acc[nt][3] * sc2 + sh2;
        if (RES) {
            float2 r1 = *(const float2*)&rb[co1 * 1024 + sp];
            float2 r2 = *(const float2*)&rb[co2 * 1024 + sp];
            o1.x += r1.x; o1.y += r1.y; o2.x += r2.x; o2.y += r2.y;
        }
        *(float2*)&ob[co1 * 1024 + sp] = o1;
        *(float2*)&ob[co2 * 1024 + sp] = o2;
    }
}

// =====================================================================
// conv k4 s2 p1 -> 64 co, BN fused. Parity-split SMEM input. (fp32x2)
// =====================================================================
template<int CIN, int OW, int C, int COPT, bool RELU>
__global__ __launch_bounds__(256) void conv4s2_t(
    const float* __restrict__ in, float* __restrict__ out,
    const float* __restrict__ w, const float* __restrict__ bias,
    const float* __restrict__ bnp)
{
    constexpr int R = 128 / OW, CPR = OW / 4, HIN = OW * 2;
    constexpr int NR = 2 * R + 2, P = OW + 1, CIST = NR * 2 * P;
    constexpr int COTILE = COPT * 8, PADW = COTILE + 4, NCOB = 64 / COTILE;
    constexpr int NP = COPT / 2;
    __shared__ __align__(16) float sIn[C * CIST];
    __shared__ __align__(16) float sW [C * 16 * PADW];
    const int t = threadIdx.x, ty = t >> 5, tx = t & 31;
    const int row = tx / CPR, col4 = (tx % CPR) * 4;
    const int bx = blockIdx.x;
    const int r0 = (bx / NCOB) * R, coBase = (bx % NCOB) * COTILE;
    const int n = blockIdx.y;
    const float* inb = in + (size_t)n * CIN * HIN * HIN;
    u64 acc[4][NP];
    #pragma unroll
    for (int j = 0; j < 4; ++j)
        #pragma unroll
        for (int p = 0; p < NP; ++p) acc[j][p] = 0ull;

    for (int ci0 = 0; ci0 < CIN; ci0 += C) {
        __syncthreads();
        for (int i = t; i < C * CIST; i += 256) {
            int ci = i / CIST, r2 = i - ci * CIST;
            int rr = r2 / (2 * P), r3 = r2 - rr * 2 * P;
            int p = r3 / P, cc = r3 - p * P;
            int gr = 2 * r0 - 1 + rr;
            int gc = 2 * cc - p;
            float v = 0.f;
            if ((unsigned)gr < (unsigned)HIN && (unsigned)gc < (unsigned)HIN)
                v = inb[(ci0 + ci) * (HIN * HIN) + gr * HIN + gc];
            sIn[i] = v;
        }
        for (int i = t; i < C * 16 * COTILE; i += 256) {
            int co = i / (C * 16), r2 = i - co * C * 16, ci = r2 >> 4, tap = r2 & 15;
            sW[ci * (16 * PADW) + tap * PADW + co] =
                w[((coBase + co) * CIN + ci0 + ci) * 16 + tap];
        }
        __syncthreads();
        #pragma unroll
        for (int ci = 0; ci < C; ++ci) {
            const float* sIb = sIn + ci * CIST + (2 * row) * (2 * P) + col4;
            const float* sWb = sW + ci * (16 * PADW) + ty * COPT;
            #pragma unroll
            for (int kh = 0; kh < 4; ++kh) {
                #pragma unroll
                for (int kw = 0; kw < 4; ++kw) {
                    const float* ip = sIb + kh * (2 * P) + ((kw & 1) ^ 1) * P + (kw >> 1);
                    const ulonglong2* wp = (const ulonglong2*)(sWb + (kh * 4 + kw) * PADW);
                    u64 wv[NP];
                    {
                        ulonglong2 wa = wp[0];
                        wv[0] = wa.x; wv[1] = wa.y;
                        if (NP == 4) {
                            ulonglong2 wb = wp[1];
                            wv[2] = wb.x; wv[3] = wb.y;
                        }
                    }
                    #pragma unroll
                    for (int j = 0; j < 4; ++j) {
                        u64 vd = dup2(ip[j]);
                        #pragma unroll
                        for (int p = 0; p < NP; ++p) ffma2(acc[j][p], vd, wv[p]);
                    }
                }
            }
        }
    }
    const int orow = r0 + row;
    #pragma unroll
    for (int p = 0; p < NP; ++p) {
        float rr2[2][4];
        #pragma unroll
        for (int j = 0; j < 4; ++j) {
            float2 ff = unpk(acc[j][p]);
            rr2[0][j] = ff.x; rr2[1][j] = ff.y;
        }
        #pragma unroll
        for (int l = 0; l < 2; ++l) {
            int co = coBase + ty * COPT + 2 * p + l;
            float b = bias[co];
            float s = bnp[co] * rsqrtf(bnp[192 + co] + 1e-5f);
            float m = bnp[128 + co], bt = bnp[64 + co];
            float r[4];
            #pragma unroll
            for (int j = 0; j < 4; ++j) {
                r[j] = (rr2[l][j] + b - m) * s + bt;
                if (RELU) r[j] = fmaxf(r[j], 0.f);
            }
            float4 o; o.x = r[0]; o.y = r[1]; o.z = r[2]; o.w = r[3];
            *(float4*)&out[((size_t)n * 64 + co) * (OW * OW) + orow * OW + col4] = o;
        }
    }
}

// =====================================================================
// conv-transpose k4 s2 p1, CIN=64. Branch-free 4-tap inner loop. (fp32x2)
// =====================================================================
template<int COUT, int OUTW, int R, bool PRERELU, bool TANH_LOSS>
__global__ __launch_bounds__(256) void convt_t(
    const float* __restrict__ in, float* __restrict__ out,
    const float* __restrict__ w, const float* __restrict__ bias,
    const float* __restrict__ xref)
{
    constexpr int HIN = OUTW / 2;
    constexpr int NRW = R + 1;
    constexpr int NC  = OUTW / 2 + 2;
    constexpr int NCP = (NC & 1) ? NC : NC + 1;
    constexpr int SPT = R * OUTW;
    constexpr int TXN = SPT / 4;
    constexpr int COS = (COUT == 64) ? 64 : 16;
    __shared__ __align__(16) float sIn[8 * NRW * NCP];
    __shared__ __align__(16) float sW [8 * 16 * 68];
    const int t = threadIdx.x, ty = t / TXN, tx = t % TXN;
    const int row = tx / (OUTW / 4), col4 = (tx % (OUTW / 4)) * 4;
    const int n = blockIdx.y, r0 = blockIdx.x * R;
    const int base_hi = ((r0 + 1) >> 1) - 1;
    const float* inb = in + (size_t)n * 64 * HIN * HIN;
    const int ho = r0 + row;
    const int kh_a = (ho + 1) & 1;
    const int rr_a = ((ho + 1) >> 1) - base_hi;
    int cc0[4], kwp[4];
    #pragma unroll
    for (int j = 0; j < 4; ++j) {
        int wo = col4 + j;
        kwp[j] = (wo + 1) & 1;
        cc0[j] = ((wo + 1) >> 1) + 1;
    }
    u64 acc[4][4];
    #pragma unroll
    for (int j = 0; j < 4; ++j)
        #pragma unroll
        for (int p = 0; p < 4; ++p) acc[j][p] = 0ull;

    for (int ci0 = 0; ci0 < 64; ci0 += 8) {
        __syncthreads();
        for (int i = t; i < 8 * NRW * NCP; i += 256) {
            int ci = i / (NRW * NCP), r2 = i - ci * (NRW * NCP);
            int rr = r2 / NCP, cc = r2 - rr * NCP;
            int gr = base_hi + rr, gc = cc - 1;
            float v = 0.f;
            if ((unsigned)gr < (unsigned)HIN && (unsigned)gc < (unsigned)HIN) {
                v = inb[(ci0 + ci) * (HIN * HIN) + gr * HIN + gc];
                if (PRERELU) v = fmaxf(v, 0.f);
            }
            sIn[i] = v;
        }
        for (int i = t; i < 8 * 16 * COS; i += 256) {
            int ci = i / (16 * COS), r2 = i - ci * (16 * COS);
            int co = r2 >> 4, tap = r2 & 15;
            float v = (co < COUT) ? w[((ci0 + ci) * COUT + co) * 16 + tap] : 0.f;
            sW[ci * 1088 + tap * 68 + co] = v;
        }
        __syncthreads();
        #pragma unroll
        for (int ci = 0; ci < 8; ++ci) {
            const float* rA = sIn + ci * (NRW * NCP) + rr_a * NCP;
            const float* rB = rA - NCP;
            const float* sWb = sW + ci * 1088 + ty * 8;
            #pragma unroll
            for (int jp = 0; jp < 2; ++jp) {
                int t0 = kh_a * 4 + kwp[jp];
                u64 wv[4][4];
                #pragma unroll
                for (int k = 0; k < 4; ++k) {
                    int tap = t0 + (k & 1) * 2 + (k >> 1) * 8;
                    const ulonglong2* wp = (const ulonglong2*)(sWb + tap * 68);
                    ulonglong2 wa = wp[0], wb = wp[1];
                    wv[k][0] = wa.x; wv[k][1] = wa.y; wv[k][2] = wb.x; wv[k][3] = wb.y;
                }
                #pragma unroll
                for (int jj = 0; jj < 2; ++jj) {
                    int j = jp + jj * 2;
                    int ca = cc0[j], cb = ca - 1;
                    u64 da = dup2(rA[ca]), db = dup2(rA[cb]);
                    u64 dc = dup2(rB[ca]), dd = dup2(rB[cb]);
                    #pragma unroll
                    for (int p = 0; p < 4; ++p) {
                        ffma2(acc[j][p], da, wv[0][p]);
                        ffma2(acc[j][p], db, wv[1][p]);
                        ffma2(acc[j][p], dc, wv[2][p]);
                        ffma2(acc[j][p], dd, wv[3][p]);
                    }
                }
            }
        }
    }
    float ls = 0.f;
    #pragma unroll
    for (int p = 0; p < 4; ++p) {
        float rr2[2][4];
        #pragma unroll
        for (int j = 0; j < 4; ++j) {
            float2 ff = unpk(acc[j][p]);
            rr2[0][j] = ff.x; rr2[1][j] = ff.y;
        }
        #pragma unroll
        for (int l = 0; l < 2; ++l) {
            int co = ty * 8 + 2 * p + l;
            if (co < COUT) {
                float b = bias[co];
                size_t oi = ((size_t)n * COUT + co) * ((size_t)OUTW * OUTW) + ho * OUTW + col4;
                float r[4];
                #pragma unroll
                for (int j = 0; j < 4; ++j) {
                    r[j] = rr2[l][j] + b;
                    if (TANH_LOSS) {
                        r[j] = tanhf(r[j]);
                        float d = r[j] - xref[oi + j];
                        ls += d * d;
                    } else {
                        r[j] = fmaxf(r[j], 0.f);
                    }
                }
                float4 o; o.x = r[0]; o.y = r[1]; o.z = r[2]; o.w = r[3];
                *(float4*)&out[oi] = o;
            }
        }
    }
    if (TANH_LOSS) {
        float s = block_sum(ls);
        if (t == 0) atomicAdd(&g_recon_ss, (double)s);
    }
}

// ---------------- VQ ----------------
__global__ void cnorm_k(const float* __restrict__ cb) {
    int k = blockIdx.x * 256 + threadIdx.x;
    if (k < 2048) {
        float s = 0.f;
        #pragma unroll
        for (int d = 0; d < 64; ++d) { float c = cb[k * 64 + d]; s += c * c; }
        g_cnorm[k] = s;
    }
}

__global__ __launch_bounds__(128) void vq_assign_k(
    const float* __restrict__ z, const float* __restrict__ cb)
{
    __shared__ __align__(16) float4 sc[128 * 16];
    __shared__ float  sn[128];
    const int row = blockIdx.x * 128 + threadIdx.x;
    const int q0 = blockIdx.y * 512;
    const int b = row >> 10, hw = row & 1023;
    u64 zr2[32];
    const float* zp = z + ((size_t)b * 64) * 1024 + hw;
    #pragma unroll
    for (int d2 = 0; d2 < 32; ++d2)
        zr2[d2] = pack2(zp[(2 * d2) * 1024], zp[(2 * d2 + 1) * 1024]);
    float best = 3.4e38f; int bi = 0;
    const float4* cb4 = (const float4*)cb;
    for (int k0 = q0; k0 < q0 + 512; k0 += 128) {
        __syncthreads();
        for (int i = threadIdx.x; i < 128 * 16; i += 128) sc[i] = cb4[k0 * 16 + i];
        sn[threadIdx.x] = g_cnorm[k0 + threadIdx.x];
        __syncthreads();
        for (int kk = 0; kk < 128; ++kk) {
            const ulonglong2* cp = (const ulonglong2*)(sc + kk * 16);
            u64 a0 = 0ull, a1 = 0ull, a2 = 0ull, a3 = 0ull;
            #pragma unroll
            for (int j = 0; j < 8; ++j) {
                ulonglong2 c0 = cp[2 * j], c1 = cp[2 * j + 1];
                ffma2(a0, zr2[4 * j + 0], c0.x);
                ffma2(a1, zr2[4 * j + 1], c0.y);
                ffma2(a2, zr2[4 * j + 2], c1.x);
                ffma2(a3, zr2[4 * j + 3], c1.y);
            }
            u64 s2 = fadd2(fadd2(a0, a1), fadd2(a2, a3));
            float2 f = unpk(s2);
            float dist = sn[kk] - 2.f * (f.x + f.y);
            if (dist < best) { best = dist; bi = k0 + kk; }
        }
    }
    unsigned int fb = __float_as_uint(best);
    unsigned int key = fb ^ (((int)fb >> 31) | 0x80000000u);
    u64 packed = ((u64)key << 32) | (unsigned)bi;
    atomicMin(&g_best[row], packed);
}

__global__ __launch_bounds__(256) void vq_gather_k(
    const float* __restrict__ z, const float* __restrict__ cb,
    float* __restrict__ quant)
{
    int gid = blockIdx.x * 256 + threadIdx.x;
    int b = gid >> 16;
    int rem = gid & 65535;
    int d = rem >> 10;
    int hw = rem & 1023;
    int k = (int)(unsigned)(g_best[(b << 10) + hw] & 0xFFFFFFFFull);
    float q = cb[k * 64 + d];
    float zv = z[gid];
    quant[gid] = q;
    float diff = q - zv;
    float s = block_sum(diff * diff);
    if (threadIdx.x == 0) atomicAdd(&g_vq_ss, (double)s);
}

__global__ void vq_counts_k() {
    int i = blockIdx.x * 256 + threadIdx.x;
    if (i < 32768) {
        int k = (int)(unsigned)(g_best[i] & 0xFFFFFFFFull);
        atomicAdd(&g_counts[k], 1.0f);
    }
}

// ---------------- finalize ----------------
__global__ void finalize_k(float* __restrict__ out2) {
    float s = 0.f;
    for (int k = threadIdx.x; k < 2048; k += 256) {
        float p = g_counts[k] * (1.0f / 32768.0f);
        s += p * logf(p + 1e-10f);
    }
    float tot = block_sum(s);
    if (threadIdx.x == 0) {
        float perp = expf(-tot);
        float loss = (float)(g_recon_ss / 31457280.0 + 1.25 * (g_vq_ss / 2097152.0));
        out2[0] = loss;
        out2[1] = perp;
    }
}

// ---------------- launcher ----------------
extern "C" void kernel_launch(void* const* d_in, const int* in_sizes, int n_in,
                              void* d_out, int out_size) {
    const float* x          = (const float*)d_in[0];
    const float* ew1        = (const float*)d_in[1];
    const float* eb1        = (const float*)d_in[2];
    const float* ew2        = (const float*)d_in[3];
    const float* eb2        = (const float*)d_in[4];
    const float* ew3        = (const float*)d_in[5];
    const float* eb3        = (const float*)d_in[6];
    const float* enc_bn     = (const float*)d_in[7];
    const float* enc_res_w3 = (const float*)d_in[8];
    const float* enc_res_b3 = (const float*)d_in[9];
    const float* enc_res_w1 = (const float*)d_in[10];
    const float* enc_res_b1 = (const float*)d_in[11];
    const float* enc_res_bn = (const float*)d_in[12];
    const float* enc_out_w  = (const float*)d_in[13];
    const float* enc_out_b  = (const float*)d_in[14];
    const float* codebook   = (const float*)d_in[15];
    const float* dec_in_w   = (const float*)d_in[16];
    const float* dec_in_b   = (const float*)d_in[17];
    const float* dec_res_w3 = (const float*)d_in[18];
    const float* dec_res_b3 = (const float*)d_in[19];
    const float* dec_res_w1 = (const float*)d_in[20];
    const float* dec_res_b1 = (const float*)d_in[21];
    const float* dec_res_bn = (const float*)d_in[22];
    const float* dt_w1      = (const float*)d_in[23];
    const float* dt_b1      = (const float*)d_in[24];
    const float* dt_w2      = (const float*)d_in[25];
    const float* dt_b2      = (const float*)d_in[26];
    const float* dt_w3      = (const float*)d_in[27];
    const float* dt_b3      = (const float*)d_in[28];

    void *pa, *pb, *pc;
    cudaGetSymbolAddress(&pa, g_bufA);
    cudaGetSymbolAddress(&pb, g_bufB);
    cudaGetSymbolAddress(&pc, g_bufC);
    float* A  = (float*)pa;
    float* Bb = (float*)pb;
    float* Cc = (float*)pc;
    float* out = (float*)d_out;

    init_k<<<128, 256>>>();

    // ---- Encoder ----
    conv4s2_t<15, 128, 5, 8, true ><<<dim3(128, 32), 256>>>(x,  A,  ew1, eb1, enc_bn);
    conv4s2_t<64, 64,  4, 8, true ><<<dim3(32, 32),  256>>>(A,  Bb, ew2, eb2, enc_bn + 256);
    conv4s2_t<64, 32,  4, 8, false><<<dim3(8, 32),   256>>>(Bb, A,  ew3, eb3, enc_bn + 512);
    for (int i = 0; i < 4; ++i) {
        conv3x3_mma<true, true><<<dim3(8, 32), 256>>>(
            A, Bb, enc_res_w3 + (size_t)i * 36864, enc_res_b3 + i * 64,
            enc_res_bn + i * 512);
        conv1x1_mma<true, true, true><<<dim3(8, 32), 256>>>(
            Bb, A, A, enc_res_w1 + (size_t)i * 4096, enc_res_b1 + i * 64,
            enc_res_bn + i * 512 + 256);
    }
    conv1x1_mma<false, false, false><<<dim3(8, 32), 256>>>(
        A, nullptr, Bb, enc_out_w, enc_out_b, nullptr);     // z -> Bb

    // ---- VQ ----
    cnorm_k<<<8, 256>>>(codebook);
    vq_assign_k<<<dim3(256, 4), 128>>>(Bb, codebook);
    vq_gather_k<<<8192, 256>>>(Bb, codebook, A);            // quant -> A
    vq_counts_k<<<128, 256>>>();

    // ---- Decoder ----
    conv3x3_mma<false, false><<<dim3(8, 32), 256>>>(A, Bb, dec_in_w, dec_in_b, nullptr);
    for (int i = 0; i < 4; ++i) {
        conv3x3_mma<true, true><<<dim3(8, 32), 256>>>(
            Bb, Cc, dec_res_w3 + (size_t)i * 36864, dec_res_b3 + i * 64,
            dec_res_bn + i * 512);
        conv1x1_mma<true, true, true><<<dim3(8, 32), 256>>>(
            Cc, Bb, Bb, dec_res_w1 + (size_t)i * 4096, dec_res_b1 + i * 64,
            dec_res_bn + i * 512 + 256);
    }
    convt_t<64, 64,  2, true,  false><<<dim3(32, 32),  256>>>(Bb, A,   dt_w1, dt_b1, nullptr);
    convt_t<64, 128, 1, false, false><<<dim3(128, 32), 256>>>(A,  Bb,  dt_w2, dt_b2, nullptr);
    convt_t<15, 256, 2, false, true ><<<dim3(128, 32), 256>>>(Bb, out, dt_w3, dt_b3, x);

    finalize_k<<<1, 256>>>(out + (out_size - 2));
}